// round 2
// baseline (speedup 1.0000x reference)
#include <cuda_runtime.h>
#include <cuda_bf16.h>
#include <math.h>

// Problem constants
#define S_LEN 2048
#define D_MODEL 2048
#define N_HEADS 32
#define N_KV 8
#define HD 64
#define KV_D (N_KV * HD)   // 512

// Scratch (static device globals: allocation-free)
__device__ float g_Q[S_LEN * D_MODEL];
__device__ float g_K[S_LEN * KV_D];
__device__ float g_V[S_LEN * KV_D];
__device__ float g_Y[S_LEN * D_MODEL];

// ---------------------------------------------------------------------------
// SGEMM: C[M,N] = A[M,K] * B[K,N], row-major, all dims multiples of tile sizes
// 128x128 block tile, BK=16, 256 threads, 8x8 per thread.
// ---------------------------------------------------------------------------
__global__ __launch_bounds__(256) void sgemm128(int M, int N, int K,
                                                const float* __restrict__ A,
                                                const float* __restrict__ B,
                                                float* __restrict__ C) {
    constexpr int BM = 128, BN = 128, BK = 16, TM = 8, TN = 8;
    __shared__ float As[BK][BM];   // transposed A tile
    __shared__ float Bs[BK][BN];

    const int tid = threadIdx.x;
    const int brow = blockIdx.y, bcol = blockIdx.x;
    const float* Ag = A + (size_t)brow * BM * K;
    const float* Bg = B + bcol * BN;
    float* Cg = C + (size_t)brow * BM * N + bcol * BN;

    const int trow = tid / (BN / TN);   // 0..15
    const int tcol = tid % (BN / TN);   // 0..15

    // load mapping
    const int aRow = tid / (BK / 4);        // 0..63
    const int aCol = (tid % (BK / 4)) * 4;  // 0,4,8,12
    const int bRow = tid / (BN / 4);        // 0..7
    const int bCol = (tid % (BN / 4)) * 4;  // 0..124

    float acc[TM][TN];
#pragma unroll
    for (int i = 0; i < TM; i++)
#pragma unroll
        for (int j = 0; j < TN; j++) acc[i][j] = 0.0f;

    float ra[TM], rb[TN];

    for (int k0 = 0; k0 < K; k0 += BK) {
#pragma unroll
        for (int r = 0; r < 2; r++) {
            float4 v = *(const float4*)(Ag + (size_t)(aRow + r * 64) * K + k0 + aCol);
            As[aCol + 0][aRow + r * 64] = v.x;
            As[aCol + 1][aRow + r * 64] = v.y;
            As[aCol + 2][aRow + r * 64] = v.z;
            As[aCol + 3][aRow + r * 64] = v.w;
        }
#pragma unroll
        for (int r = 0; r < 2; r++) {
            *(float4*)(&Bs[bRow + r * 8][bCol]) =
                *(const float4*)(Bg + (size_t)(k0 + bRow + r * 8) * N + bCol);
        }
        __syncthreads();

#pragma unroll
        for (int k = 0; k < BK; k++) {
#pragma unroll
            for (int i = 0; i < TM; i++) ra[i] = As[k][trow * TM + i];
#pragma unroll
            for (int j = 0; j < TN; j++) rb[j] = Bs[k][tcol * TN + j];
#pragma unroll
            for (int i = 0; i < TM; i++)
#pragma unroll
                for (int j = 0; j < TN; j++) acc[i][j] += ra[i] * rb[j];
        }
        __syncthreads();
    }

#pragma unroll
    for (int i = 0; i < TM; i++) {
#pragma unroll
        for (int j = 0; j < TN; j += 4) {
            float4 v = make_float4(acc[i][j], acc[i][j + 1], acc[i][j + 2], acc[i][j + 3]);
            *(float4*)(Cg + (size_t)(trow * TM + i) * N + tcol * TN + j) = v;
        }
    }
}

// ---------------------------------------------------------------------------
// RoPE in-place on a [S, N_KV*HD] tensor. Pairs are adjacent (2i, 2i+1).
// cos/sin: [S, HD/2]
// ---------------------------------------------------------------------------
__global__ void rope_kernel(float* __restrict__ t,
                            const float* __restrict__ cosv,
                            const float* __restrict__ sinv) {
    int idx = blockIdx.x * blockDim.x + threadIdx.x;
    const int total = S_LEN * N_KV * (HD / 2);
    if (idx >= total) return;
    int i = idx % (HD / 2);
    int kvh = (idx / (HD / 2)) % N_KV;
    int s = idx / ((HD / 2) * N_KV);
    float* p = t + (size_t)s * KV_D + kvh * HD + 2 * i;
    float c = cosv[s * (HD / 2) + i];
    float sn = sinv[s * (HD / 2) + i];
    float a = p[0], b = p[1];
    p[0] = a * c - b * sn;
    p[1] = a * sn + b * c;
}

// ---------------------------------------------------------------------------
// Flash-attention style causal attention.
// Q: [S, 32*64]   K,V: [S, 8*64]   Y: [S, 32*64]
// Block: (q_tile of 64 rows, head). 256 threads. K-tiles of 64 keys.
// Online softmax; O accumulator in registers (4x4 per thread).
// ---------------------------------------------------------------------------
#define AP 65   // smem row stride (padding)
#define ATTN_SMEM_BYTES ((4 * 64 * AP + 3 * 64) * 4)

__global__ __launch_bounds__(256) void attn_kernel(const float* __restrict__ Q,
                                                   const float* __restrict__ K,
                                                   const float* __restrict__ V,
                                                   float* __restrict__ Y) {
    extern __shared__ float sm[];
    float* Qs = sm;                  // 64 x AP
    float* Ks = Qs + 64 * AP;        // 64 x AP
    float* Vs = Ks + 64 * AP;        // 64 x AP
    float* Ps = Vs + 64 * AP;        // 64 x AP (scores, then probabilities)
    float* m_s = Ps + 64 * AP;       // 64
    float* l_s = m_s + 64;           // 64
    float* al_s = l_s + 64;          // 64

    const int tid = threadIdx.x;
    const int qt = blockIdx.x;           // q tile index (0..31)
    const int h = blockIdx.y;            // head (0..31)
    const int kvh = h >> 2;              // GQA: 4 q heads per kv head
    const int q0 = qt * 64;

    const int ty = tid >> 4;   // 0..15 (row group)
    const int tx = tid & 15;   // 0..15 (col group)

    // Load Q tile: 64 rows x 64 dims
    for (int i = tid; i < 64 * 16; i += 256) {
        int r = i / 16, c4 = (i % 16) * 4;
        float4 v = *(const float4*)(Q + (size_t)(q0 + r) * D_MODEL + h * HD + c4);
        Qs[r * AP + c4 + 0] = v.x;
        Qs[r * AP + c4 + 1] = v.y;
        Qs[r * AP + c4 + 2] = v.z;
        Qs[r * AP + c4 + 3] = v.w;
    }
    if (tid < 64) { m_s[tid] = -INFINITY; l_s[tid] = 0.0f; }

    float o[4][4];
#pragma unroll
    for (int i = 0; i < 4; i++)
#pragma unroll
        for (int j = 0; j < 4; j++) o[i][j] = 0.0f;

    __syncthreads();

    const float scale = 0.125f;  // hd^-0.5 for hd=64

    for (int kt = 0; kt <= qt; kt++) {
        const int k0 = kt * 64;
        // Load K and V tiles
        for (int i = tid; i < 64 * 16; i += 256) {
            int r = i / 16, c4 = (i % 16) * 4;
            float4 kv4 = *(const float4*)(K + (size_t)(k0 + r) * KV_D + kvh * HD + c4);
            Ks[r * AP + c4 + 0] = kv4.x;
            Ks[r * AP + c4 + 1] = kv4.y;
            Ks[r * AP + c4 + 2] = kv4.z;
            Ks[r * AP + c4 + 3] = kv4.w;
            float4 vv4 = *(const float4*)(V + (size_t)(k0 + r) * KV_D + kvh * HD + c4);
            Vs[r * AP + c4 + 0] = vv4.x;
            Vs[r * AP + c4 + 1] = vv4.y;
            Vs[r * AP + c4 + 2] = vv4.z;
            Vs[r * AP + c4 + 3] = vv4.w;
        }
        __syncthreads();

        // S = Q * K^T (4x4 per thread)
        float acc[4][4];
#pragma unroll
        for (int i = 0; i < 4; i++)
#pragma unroll
            for (int j = 0; j < 4; j++) acc[i][j] = 0.0f;

#pragma unroll 8
        for (int d = 0; d < 64; d++) {
            float qv[4], kv[4];
#pragma unroll
            for (int ii = 0; ii < 4; ii++) qv[ii] = Qs[(ty * 4 + ii) * AP + d];
#pragma unroll
            for (int jj = 0; jj < 4; jj++) kv[jj] = Ks[(tx * 4 + jj) * AP + d];
#pragma unroll
            for (int ii = 0; ii < 4; ii++)
#pragma unroll
                for (int jj = 0; jj < 4; jj++) acc[ii][jj] += qv[ii] * kv[jj];
        }
#pragma unroll
        for (int ii = 0; ii < 4; ii++) {
            int gr = q0 + ty * 4 + ii;
#pragma unroll
            for (int jj = 0; jj < 4; jj++) {
                int gc = k0 + tx * 4 + jj;
                Ps[(ty * 4 + ii) * AP + tx * 4 + jj] =
                    (gc <= gr) ? acc[ii][jj] * scale : -INFINITY;
            }
        }
        __syncthreads();

        // Online softmax row update (one thread per row)
        if (tid < 64) {
            int r = tid;
            float mo = m_s[r];
            float tmax = -INFINITY;
#pragma unroll 8
            for (int j = 0; j < 64; j++) tmax = fmaxf(tmax, Ps[r * AP + j]);
            float mn = fmaxf(mo, tmax);
            float a = __expf(mo - mn);   // first tile: exp(-inf)=0
            float rs = 0.0f;
#pragma unroll 8
            for (int j = 0; j < 64; j++) {
                float p = __expf(Ps[r * AP + j] - mn);
                Ps[r * AP + j] = p;
                rs += p;
            }
            l_s[r] = l_s[r] * a + rs;
            m_s[r] = mn;
            al_s[r] = a;
        }
        __syncthreads();

        // O = O*alpha + P @ V (4x4 per thread over (row, out-dim))
#pragma unroll
        for (int ii = 0; ii < 4; ii++) {
            float a = al_s[ty * 4 + ii];
#pragma unroll
            for (int dd = 0; dd < 4; dd++) o[ii][dd] *= a;
        }
#pragma unroll 4
        for (int j = 0; j < 64; j++) {
            float vv[4];
#pragma unroll
            for (int dd = 0; dd < 4; dd++) vv[dd] = Vs[j * AP + tx * 4 + dd];
#pragma unroll
            for (int ii = 0; ii < 4; ii++) {
                float p = Ps[(ty * 4 + ii) * AP + j];
#pragma unroll
                for (int dd = 0; dd < 4; dd++) o[ii][dd] += p * vv[dd];
            }
        }
        __syncthreads();
    }

    // Final normalize + write
#pragma unroll
    for (int ii = 0; ii < 4; ii++) {
        int r = ty * 4 + ii;
        float inv = 1.0f / l_s[r];
#pragma unroll
        for (int dd = 0; dd < 4; dd++) {
            Y[(size_t)(q0 + r) * D_MODEL + h * HD + tx * 4 + dd] = o[ii][dd] * inv;
        }
    }
}

// ---------------------------------------------------------------------------
// Launch
// ---------------------------------------------------------------------------
extern "C" void kernel_launch(void* const* d_in, const int* in_sizes, int n_in,
                              void* d_out, int out_size) {
    const float* x  = (const float*)d_in[0];
    const float* tc = (const float*)d_in[1];
    const float* ts = (const float*)d_in[2];
    const float* wq = (const float*)d_in[3];
    const float* wk = (const float*)d_in[4];
    const float* wv = (const float*)d_in[5];
    const float* wo = (const float*)d_in[6];
    float* out = (float*)d_out;

    float *Q, *K, *V, *Y;
    cudaGetSymbolAddress((void**)&Q, g_Q);
    cudaGetSymbolAddress((void**)&K, g_K);
    cudaGetSymbolAddress((void**)&V, g_V);
    cudaGetSymbolAddress((void**)&Y, g_Y);

    cudaFuncSetAttribute(attn_kernel, cudaFuncAttributeMaxDynamicSharedMemorySize,
                         ATTN_SMEM_BYTES);

    // Projections
    sgemm128<<<dim3(D_MODEL / 128, S_LEN / 128), 256>>>(S_LEN, D_MODEL, D_MODEL, x, wq, Q);
    sgemm128<<<dim3(KV_D / 128, S_LEN / 128), 256>>>(S_LEN, KV_D, D_MODEL, x, wk, K);
    sgemm128<<<dim3(KV_D / 128, S_LEN / 128), 256>>>(S_LEN, KV_D, D_MODEL, x, wv, V);

    // RoPE on K and V
    const int rope_total = S_LEN * N_KV * (HD / 2);
    rope_kernel<<<(rope_total + 255) / 256, 256>>>(K, tc, ts);
    rope_kernel<<<(rope_total + 255) / 256, 256>>>(V, tc, ts);

    // Attention
    attn_kernel<<<dim3(S_LEN / 64, N_HEADS), 256, ATTN_SMEM_BYTES>>>(Q, K, V, Y);

    // Output projection
    sgemm128<<<dim3(D_MODEL / 128, S_LEN / 128), 256>>>(S_LEN, D_MODEL, D_MODEL, Y, wo, out);
}

// round 8
// speedup vs baseline: 1.6371x; 1.6371x over previous
#include <cuda_runtime.h>
#include <cuda_bf16.h>
#include <math.h>
#include <stdint.h>

// Problem constants
#define S_LEN 2048
#define D_MODEL 2048
#define N_HEADS 32
#define N_KV 8
#define HD 64
#define KV_D (N_KV * HD)   // 512

// ---------------------------------------------------------------------------
// Scratch (static device globals: allocation-free)
// ---------------------------------------------------------------------------
__device__ float g_Q[S_LEN * D_MODEL];
__device__ float g_K[S_LEN * KV_D];
__device__ float g_V[S_LEN * KV_D];
__device__ float g_Y[S_LEN * D_MODEL];

// bf16 split operands
__device__ __nv_bfloat16 g_Ah[S_LEN * D_MODEL];
__device__ __nv_bfloat16 g_Al[S_LEN * D_MODEL];
__device__ __nv_bfloat16 g_Yh[S_LEN * D_MODEL];
__device__ __nv_bfloat16 g_Yl[S_LEN * D_MODEL];
// transposed weights [N, K] bf16 hi/lo
__device__ __nv_bfloat16 g_Wqh[D_MODEL * D_MODEL];
__device__ __nv_bfloat16 g_Wql[D_MODEL * D_MODEL];
__device__ __nv_bfloat16 g_Wkh[KV_D * D_MODEL];
__device__ __nv_bfloat16 g_Wkl[KV_D * D_MODEL];
__device__ __nv_bfloat16 g_Wvh[KV_D * D_MODEL];
__device__ __nv_bfloat16 g_Wvl[KV_D * D_MODEL];
__device__ __nv_bfloat16 g_Woh[D_MODEL * D_MODEL];
__device__ __nv_bfloat16 g_Wol[D_MODEL * D_MODEL];

// ---------------------------------------------------------------------------
// Portable helpers (NO sm_103a-specific instructions: ptxas here targets sm_103)
// ---------------------------------------------------------------------------
__device__ __forceinline__ unsigned smem_u32(const void* p) {
    unsigned a;
    asm("{ .reg .u64 t; cvta.to.shared.u64 t, %1; cvt.u32.u64 %0, t; }"
        : "=r"(a) : "l"(p));
    return a;
}
__device__ __forceinline__ void cp_async16(unsigned dst, const void* src) {
    asm volatile("cp.async.cg.shared.global [%0], [%1], 16;"
                 :: "r"(dst), "l"(src));
}
#define CP_COMMIT() asm volatile("cp.async.commit_group;" ::: "memory")
#define CP_WAIT(n)  asm volatile("cp.async.wait_group %0;" :: "n"(n) : "memory")

// mma.sync m16n8k16 bf16 -> f32 (portable HMMA path)
__device__ __forceinline__ void mma16816(float* c, const unsigned* a, const unsigned* b) {
    asm volatile(
        "mma.sync.aligned.m16n8k16.row.col.f32.bf16.bf16.f32 "
        "{%0,%1,%2,%3}, {%4,%5,%6,%7}, {%8,%9}, {%0,%1,%2,%3};"
        : "+f"(c[0]), "+f"(c[1]), "+f"(c[2]), "+f"(c[3])
        : "r"(a[0]), "r"(a[1]), "r"(a[2]), "r"(a[3]), "r"(b[0]), "r"(b[1]));
}

// ---------------------------------------------------------------------------
// Split fp32 -> bf16 hi/lo (vectorized, n4 = elements/4)
// ---------------------------------------------------------------------------
__global__ void split_kernel(const float* __restrict__ src,
                             __nv_bfloat16* __restrict__ hi,
                             __nv_bfloat16* __restrict__ lo, int n4) {
    int i = blockIdx.x * blockDim.x + threadIdx.x;
    if (i >= n4) return;
    float4 v = ((const float4*)src)[i];
    __nv_bfloat16 h0 = __float2bfloat16(v.x), h1 = __float2bfloat16(v.y);
    __nv_bfloat16 h2 = __float2bfloat16(v.z), h3 = __float2bfloat16(v.w);
    __nv_bfloat16 l0 = __float2bfloat16(v.x - __bfloat162float(h0));
    __nv_bfloat16 l1 = __float2bfloat16(v.y - __bfloat162float(h1));
    __nv_bfloat16 l2 = __float2bfloat16(v.z - __bfloat162float(h2));
    __nv_bfloat16 l3 = __float2bfloat16(v.w - __bfloat162float(h3));
    ((__nv_bfloat162*)hi)[2 * i]     = __nv_bfloat162(h0, h1);
    ((__nv_bfloat162*)hi)[2 * i + 1] = __nv_bfloat162(h2, h3);
    ((__nv_bfloat162*)lo)[2 * i]     = __nv_bfloat162(l0, l1);
    ((__nv_bfloat162*)lo)[2 * i + 1] = __nv_bfloat162(l2, l3);
}

// ---------------------------------------------------------------------------
// Transpose + split: w[K,N] f32 -> wt[N,K] bf16 hi/lo
// ---------------------------------------------------------------------------
__global__ void transpose_split(const float* __restrict__ w,
                                __nv_bfloat16* __restrict__ th,
                                __nv_bfloat16* __restrict__ tl,
                                int Kdim, int Ndim) {
    __shared__ float tile[32][33];
    int n0 = blockIdx.x * 32, k0 = blockIdx.y * 32;
    int tx = threadIdx.x, ty = threadIdx.y;   // 32 x 8
    for (int r = ty; r < 32; r += 8)
        tile[r][tx] = w[(size_t)(k0 + r) * Ndim + n0 + tx];
    __syncthreads();
    for (int r = ty; r < 32; r += 8) {
        float v = tile[tx][r];
        __nv_bfloat16 h = __float2bfloat16(v);
        __nv_bfloat16 l = __float2bfloat16(v - __bfloat162float(h));
        size_t o = (size_t)(n0 + r) * Kdim + k0 + tx;
        th[o] = h;
        tl[o] = l;
    }
}

// ---------------------------------------------------------------------------
// mma.sync bf16x3 GEMM: C[M,N] = A[M,K] * Bt[N,K]^T  (fp32-accurate)
// BM=128 BN=128 BK=32, 256 threads (8 warps, 2x4), warp tile 64x32.
// cp.async double-buffered smem; padded stride 40 bf16 (80 B) -> conflict-free.
// ---------------------------------------------------------------------------
#define LDS_S 40                 // smem row stride in bf16 elements
#define TILE_E (128 * LDS_S)     // 5120 elements = 10240 bytes per operand tile
#define BUF_E (4 * TILE_E)       // 20480 elements per buffer
#define GEMM_SMEM_BYTES (2 * BUF_E * 2)   // 81920 bytes

__global__ __launch_bounds__(256, 1)
void gemm_mma(int M, int N, int K,
              const __nv_bfloat16* __restrict__ Ah,
              const __nv_bfloat16* __restrict__ Al,
              const __nv_bfloat16* __restrict__ Bh,
              const __nv_bfloat16* __restrict__ Bl,
              float* __restrict__ C) {
    extern __shared__ __align__(16) __nv_bfloat16 s[];
    const int tid = threadIdx.x;
    const int wid = tid >> 5, lane = tid & 31;
    const int m0 = blockIdx.y * 128, n0 = blockIdx.x * 128;
    const int wm = (wid >> 2) * 64;   // warp m offset (0 or 64)
    const int wn = (wid & 3) * 32;    // warp n offset (0,32,64,96)
    const unsigned sbase = smem_u32(s);

    const int nch = K >> 5;   // K/32 chunks

    // async-load one K-chunk (4 operand tiles of 128 rows x 32 bf16) into buffer
    auto issue = [&](int c, int buf) {
        const int k0 = c << 5;
        const unsigned b0 = sbase + buf * (BUF_E * 2);
#pragma unroll
        for (int it = 0; it < 2; it++) {
            const int idx = tid + it * 256;          // 0..511
            const int row = idx >> 2, seg = idx & 3; // 4 x 16B segs per row
            const unsigned so = (unsigned)(row * (LDS_S * 2) + seg * 16);
            const size_t ga = (size_t)(m0 + row) * K + k0 + seg * 8;
            const size_t gb = (size_t)(n0 + row) * K + k0 + seg * 8;
            cp_async16(b0 + so,                 Ah + ga);
            cp_async16(b0 + TILE_E * 2 + so,     Al + ga);
            cp_async16(b0 + TILE_E * 4 + so,     Bh + gb);
            cp_async16(b0 + TILE_E * 6 + so,     Bl + gb);
        }
    };

    float acc[4][4][4];
#pragma unroll
    for (int i = 0; i < 4; i++)
#pragma unroll
        for (int j = 0; j < 4; j++)
#pragma unroll
            for (int k = 0; k < 4; k++) acc[i][j][k] = 0.0f;

    issue(0, 0);
    CP_COMMIT();

    const int r = lane >> 2;          // groupID 0..7
    const int q = (lane & 3) * 2;     // k-pair offset

    for (int c = 0; c < nch; c++) {
        if (c + 1 < nch) {
            issue(c + 1, (c + 1) & 1);
            CP_COMMIT();
            CP_WAIT(1);
        } else {
            CP_WAIT(0);
        }
        __syncthreads();

        const __nv_bfloat16* sb = s + (c & 1) * BUF_E;
        const __nv_bfloat16* sAh = sb;
        const __nv_bfloat16* sAl = sb + TILE_E;
        const __nv_bfloat16* sBh = sb + 2 * TILE_E;
        const __nv_bfloat16* sBl = sb + 3 * TILE_E;

#pragma unroll
        for (int kk = 0; kk < 2; kk++) {
            const int kc = kk * 16;
            unsigned ah[4][4], al[4][4], bh[4][2], bl[4][2];
#pragma unroll
            for (int mi = 0; mi < 4; mi++) {
                const int rb = (wm + mi * 16 + r) * LDS_S + kc + q;
                ah[mi][0] = *(const unsigned*)(sAh + rb);
                ah[mi][1] = *(const unsigned*)(sAh + rb + 8 * LDS_S);
                ah[mi][2] = *(const unsigned*)(sAh + rb + 8);
                ah[mi][3] = *(const unsigned*)(sAh + rb + 8 * LDS_S + 8);
                al[mi][0] = *(const unsigned*)(sAl + rb);
                al[mi][1] = *(const unsigned*)(sAl + rb + 8 * LDS_S);
                al[mi][2] = *(const unsigned*)(sAl + rb + 8);
                al[mi][3] = *(const unsigned*)(sAl + rb + 8 * LDS_S + 8);
            }
#pragma unroll
            for (int ni = 0; ni < 4; ni++) {
                const int rb = (wn + ni * 8 + r) * LDS_S + kc + q;
                bh[ni][0] = *(const unsigned*)(sBh + rb);
                bh[ni][1] = *(const unsigned*)(sBh + rb + 8);
                bl[ni][0] = *(const unsigned*)(sBl + rb);
                bl[ni][1] = *(const unsigned*)(sBl + rb + 8);
            }
#pragma unroll
            for (int mi = 0; mi < 4; mi++)
#pragma unroll
                for (int ni = 0; ni < 4; ni++) {
                    mma16816(acc[mi][ni], ah[mi], bh[ni]);
                    mma16816(acc[mi][ni], ah[mi], bl[ni]);
                    mma16816(acc[mi][ni], al[mi], bh[ni]);
                }
        }
        __syncthreads();
    }

    // Epilogue: C fragment layout c0,c1=(row r, col q..q+1), c2,c3=(row r+8)
#pragma unroll
    for (int mi = 0; mi < 4; mi++) {
#pragma unroll
        for (int ni = 0; ni < 4; ni++) {
            const int row = m0 + wm + mi * 16 + r;
            const int col = n0 + wn + ni * 8 + q;
            *(float2*)(C + (size_t)row * N + col) =
                make_float2(acc[mi][ni][0], acc[mi][ni][1]);
            *(float2*)(C + (size_t)(row + 8) * N + col) =
                make_float2(acc[mi][ni][2], acc[mi][ni][3]);
        }
    }
}

// ---------------------------------------------------------------------------
// RoPE in-place on a [S, N_KV*HD] tensor. Pairs are adjacent (2i, 2i+1).
// ---------------------------------------------------------------------------
__global__ void rope_kernel(float* __restrict__ t,
                            const float* __restrict__ cosv,
                            const float* __restrict__ sinv) {
    int idx = blockIdx.x * blockDim.x + threadIdx.x;
    const int total = S_LEN * N_KV * (HD / 2);
    if (idx >= total) return;
    int i = idx % (HD / 2);
    int kvh = (idx / (HD / 2)) % N_KV;
    int s = idx / ((HD / 2) * N_KV);
    float* p = t + (size_t)s * KV_D + kvh * HD + 2 * i;
    float c = cosv[s * (HD / 2) + i];
    float sn = sinv[s * (HD / 2) + i];
    float a = p[0], b = p[1];
    p[0] = a * c - b * sn;
    p[1] = a * sn + b * c;
}

// ---------------------------------------------------------------------------
// Flash-attention style causal attention (fp32; unchanged, known-good).
// ---------------------------------------------------------------------------
#define AP 65
#define ATTN_SMEM_BYTES ((4 * 64 * AP + 3 * 64) * 4)

__global__ __launch_bounds__(256) void attn_kernel(const float* __restrict__ Q,
                                                   const float* __restrict__ K,
                                                   const float* __restrict__ V,
                                                   float* __restrict__ Y) {
    extern __shared__ float sm[];
    float* Qs = sm;
    float* Ks = Qs + 64 * AP;
    float* Vs = Ks + 64 * AP;
    float* Ps = Vs + 64 * AP;
    float* m_s = Ps + 64 * AP;
    float* l_s = m_s + 64;
    float* al_s = l_s + 64;

    const int tid = threadIdx.x;
    const int qt = blockIdx.x;
    const int h = blockIdx.y;
    const int kvh = h >> 2;
    const int q0 = qt * 64;

    const int ty = tid >> 4;
    const int tx = tid & 15;

    for (int i = tid; i < 64 * 16; i += 256) {
        int r = i / 16, c4 = (i % 16) * 4;
        float4 v = *(const float4*)(Q + (size_t)(q0 + r) * D_MODEL + h * HD + c4);
        Qs[r * AP + c4 + 0] = v.x;
        Qs[r * AP + c4 + 1] = v.y;
        Qs[r * AP + c4 + 2] = v.z;
        Qs[r * AP + c4 + 3] = v.w;
    }
    if (tid < 64) { m_s[tid] = -INFINITY; l_s[tid] = 0.0f; }

    float o[4][4];
#pragma unroll
    for (int i = 0; i < 4; i++)
#pragma unroll
        for (int j = 0; j < 4; j++) o[i][j] = 0.0f;

    __syncthreads();

    const float scale = 0.125f;

    for (int kt = 0; kt <= qt; kt++) {
        const int k0 = kt * 64;
        for (int i = tid; i < 64 * 16; i += 256) {
            int r = i / 16, c4 = (i % 16) * 4;
            float4 kv4 = *(const float4*)(K + (size_t)(k0 + r) * KV_D + kvh * HD + c4);
            Ks[r * AP + c4 + 0] = kv4.x;
            Ks[r * AP + c4 + 1] = kv4.y;
            Ks[r * AP + c4 + 2] = kv4.z;
            Ks[r * AP + c4 + 3] = kv4.w;
            float4 vv4 = *(const float4*)(V + (size_t)(k0 + r) * KV_D + kvh * HD + c4);
            Vs[r * AP + c4 + 0] = vv4.x;
            Vs[r * AP + c4 + 1] = vv4.y;
            Vs[r * AP + c4 + 2] = vv4.z;
            Vs[r * AP + c4 + 3] = vv4.w;
        }
        __syncthreads();

        float acc[4][4];
#pragma unroll
        for (int i = 0; i < 4; i++)
#pragma unroll
            for (int j = 0; j < 4; j++) acc[i][j] = 0.0f;

#pragma unroll 8
        for (int d = 0; d < 64; d++) {
            float qv[4], kv[4];
#pragma unroll
            for (int ii = 0; ii < 4; ii++) qv[ii] = Qs[(ty * 4 + ii) * AP + d];
#pragma unroll
            for (int jj = 0; jj < 4; jj++) kv[jj] = Ks[(tx * 4 + jj) * AP + d];
#pragma unroll
            for (int ii = 0; ii < 4; ii++)
#pragma unroll
                for (int jj = 0; jj < 4; jj++) acc[ii][jj] += qv[ii] * kv[jj];
        }
#pragma unroll
        for (int ii = 0; ii < 4; ii++) {
            int gr = q0 + ty * 4 + ii;
#pragma unroll
            for (int jj = 0; jj < 4; jj++) {
                int gc = k0 + tx * 4 + jj;
                Ps[(ty * 4 + ii) * AP + tx * 4 + jj] =
                    (gc <= gr) ? acc[ii][jj] * scale : -INFINITY;
            }
        }
        __syncthreads();

        if (tid < 64) {
            int r = tid;
            float mo = m_s[r];
            float tmax = -INFINITY;
#pragma unroll 8
            for (int j = 0; j < 64; j++) tmax = fmaxf(tmax, Ps[r * AP + j]);
            float mn = fmaxf(mo, tmax);
            float a = __expf(mo - mn);
            float rs = 0.0f;
#pragma unroll 8
            for (int j = 0; j < 64; j++) {
                float p = __expf(Ps[r * AP + j] - mn);
                Ps[r * AP + j] = p;
                rs += p;
            }
            l_s[r] = l_s[r] * a + rs;
            m_s[r] = mn;
            al_s[r] = a;
        }
        __syncthreads();

#pragma unroll
        for (int ii = 0; ii < 4; ii++) {
            float a = al_s[ty * 4 + ii];
#pragma unroll
            for (int dd = 0; dd < 4; dd++) o[ii][dd] *= a;
        }
#pragma unroll 4
        for (int j = 0; j < 64; j++) {
            float vv[4];
#pragma unroll
            for (int dd = 0; dd < 4; dd++) vv[dd] = Vs[j * AP + tx * 4 + dd];
#pragma unroll
            for (int ii = 0; ii < 4; ii++) {
                float p = Ps[(ty * 4 + ii) * AP + j];
#pragma unroll
                for (int dd = 0; dd < 4; dd++) o[ii][dd] += p * vv[dd];
            }
        }
        __syncthreads();
    }

#pragma unroll
    for (int ii = 0; ii < 4; ii++) {
        int r = ty * 4 + ii;
        float inv = 1.0f / l_s[r];
#pragma unroll
        for (int dd = 0; dd < 4; dd++) {
            Y[(size_t)(q0 + r) * D_MODEL + h * HD + tx * 4 + dd] = o[ii][dd] * inv;
        }
    }
}

// ---------------------------------------------------------------------------
// Launch
// ---------------------------------------------------------------------------
extern "C" void kernel_launch(void* const* d_in, const int* in_sizes, int n_in,
                              void* d_out, int out_size) {
    const float* x  = (const float*)d_in[0];
    const float* tc = (const float*)d_in[1];
    const float* ts = (const float*)d_in[2];
    const float* wq = (const float*)d_in[3];
    const float* wk = (const float*)d_in[4];
    const float* wv = (const float*)d_in[5];
    const float* wo = (const float*)d_in[6];
    float* out = (float*)d_out;

    float *Q, *K, *V, *Y;
    cudaGetSymbolAddress((void**)&Q, g_Q);
    cudaGetSymbolAddress((void**)&K, g_K);
    cudaGetSymbolAddress((void**)&V, g_V);
    cudaGetSymbolAddress((void**)&Y, g_Y);
    __nv_bfloat16 *Ah, *Al, *Yh, *Yl, *Wqh, *Wql, *Wkh, *Wkl, *Wvh, *Wvl, *Woh, *Wol;
    cudaGetSymbolAddress((void**)&Ah, g_Ah);
    cudaGetSymbolAddress((void**)&Al, g_Al);
    cudaGetSymbolAddress((void**)&Yh, g_Yh);
    cudaGetSymbolAddress((void**)&Yl, g_Yl);
    cudaGetSymbolAddress((void**)&Wqh, g_Wqh);
    cudaGetSymbolAddress((void**)&Wql, g_Wql);
    cudaGetSymbolAddress((void**)&Wkh, g_Wkh);
    cudaGetSymbolAddress((void**)&Wkl, g_Wkl);
    cudaGetSymbolAddress((void**)&Wvh, g_Wvh);
    cudaGetSymbolAddress((void**)&Wvl, g_Wvl);
    cudaGetSymbolAddress((void**)&Woh, g_Woh);
    cudaGetSymbolAddress((void**)&Wol, g_Wol);

    cudaFuncSetAttribute(attn_kernel, cudaFuncAttributeMaxDynamicSharedMemorySize,
                         ATTN_SMEM_BYTES);
    cudaFuncSetAttribute(gemm_mma, cudaFuncAttributeMaxDynamicSharedMemorySize,
                         GEMM_SMEM_BYTES);

    // Split x -> bf16 hi/lo
    const int n4x = S_LEN * D_MODEL / 4;
    split_kernel<<<(n4x + 255) / 256, 256>>>(x, Ah, Al, n4x);

    // Transpose + split weights -> [N, K] bf16 hi/lo
    transpose_split<<<dim3(D_MODEL / 32, D_MODEL / 32), dim3(32, 8)>>>(wq, Wqh, Wql, D_MODEL, D_MODEL);
    transpose_split<<<dim3(KV_D / 32, D_MODEL / 32), dim3(32, 8)>>>(wk, Wkh, Wkl, D_MODEL, KV_D);
    transpose_split<<<dim3(KV_D / 32, D_MODEL / 32), dim3(32, 8)>>>(wv, Wvh, Wvl, D_MODEL, KV_D);
    transpose_split<<<dim3(D_MODEL / 32, D_MODEL / 32), dim3(32, 8)>>>(wo, Woh, Wol, D_MODEL, D_MODEL);

    // Projections on mma.sync (bf16x3)
    gemm_mma<<<dim3(D_MODEL / 128, S_LEN / 128), 256, GEMM_SMEM_BYTES>>>(
        S_LEN, D_MODEL, D_MODEL, Ah, Al, Wqh, Wql, Q);
    gemm_mma<<<dim3(KV_D / 128, S_LEN / 128), 256, GEMM_SMEM_BYTES>>>(
        S_LEN, KV_D, D_MODEL, Ah, Al, Wkh, Wkl, K);
    gemm_mma<<<dim3(KV_D / 128, S_LEN / 128), 256, GEMM_SMEM_BYTES>>>(
        S_LEN, KV_D, D_MODEL, Ah, Al, Wvh, Wvl, V);

    // RoPE on K and V
    const int rope_total = S_LEN * N_KV * (HD / 2);
    rope_kernel<<<(rope_total + 255) / 256, 256>>>(K, tc, ts);
    rope_kernel<<<(rope_total + 255) / 256, 256>>>(V, tc, ts);

    // Attention (fp32)
    attn_kernel<<<dim3(S_LEN / 64, N_HEADS), 256, ATTN_SMEM_BYTES>>>(Q, K, V, Y);

    // Split Y and output projection on mma.sync
    split_kernel<<<(n4x + 255) / 256, 256>>>(Y, Yh, Yl, n4x);
    gemm_mma<<<dim3(D_MODEL / 128, S_LEN / 128), 256, GEMM_SMEM_BYTES>>>(
        S_LEN, D_MODEL, D_MODEL, Yh, Yl, Woh, Wol, out);
}

// round 10
// speedup vs baseline: 2.7284x; 1.6666x over previous
#include <cuda_runtime.h>
#include <cuda_bf16.h>
#include <math.h>
#include <stdint.h>

// Problem constants
#define S_LEN 2048
#define D_MODEL 2048
#define N_HEADS 32
#define N_KV 8
#define HD 64
#define KV_D (N_KV * HD)   // 512

// ---------------------------------------------------------------------------
// Scratch (static device globals: allocation-free)
// ---------------------------------------------------------------------------
__device__ float g_Q[S_LEN * D_MODEL];
__device__ float g_K[S_LEN * KV_D];
__device__ float g_V[S_LEN * KV_D];

// bf16 split operands
__device__ __nv_bfloat16 g_Ah[S_LEN * D_MODEL];
__device__ __nv_bfloat16 g_Al[S_LEN * D_MODEL];
__device__ __nv_bfloat16 g_Qh[S_LEN * D_MODEL];
__device__ __nv_bfloat16 g_Ql[S_LEN * D_MODEL];
__device__ __nv_bfloat16 g_Kh[S_LEN * KV_D];
__device__ __nv_bfloat16 g_Kl[S_LEN * KV_D];
__device__ __nv_bfloat16 g_Vh[S_LEN * KV_D];
__device__ __nv_bfloat16 g_Vl[S_LEN * KV_D];
__device__ __nv_bfloat16 g_Yh[S_LEN * D_MODEL];
__device__ __nv_bfloat16 g_Yl[S_LEN * D_MODEL];
// transposed weights [N, K] bf16 hi/lo
__device__ __nv_bfloat16 g_Wqh[D_MODEL * D_MODEL];
__device__ __nv_bfloat16 g_Wql[D_MODEL * D_MODEL];
__device__ __nv_bfloat16 g_Wkh[KV_D * D_MODEL];
__device__ __nv_bfloat16 g_Wkl[KV_D * D_MODEL];
__device__ __nv_bfloat16 g_Wvh[KV_D * D_MODEL];
__device__ __nv_bfloat16 g_Wvl[KV_D * D_MODEL];
__device__ __nv_bfloat16 g_Woh[D_MODEL * D_MODEL];
__device__ __nv_bfloat16 g_Wol[D_MODEL * D_MODEL];

// ---------------------------------------------------------------------------
// Portable helpers (ptxas here targets sm_103 — no tcgen05/sm_103a-only ops)
// ---------------------------------------------------------------------------
__device__ __forceinline__ unsigned smem_u32(const void* p) {
    unsigned a;
    asm("{ .reg .u64 t; cvta.to.shared.u64 t, %1; cvt.u32.u64 %0, t; }"
        : "=r"(a) : "l"(p));
    return a;
}
__device__ __forceinline__ void cp_async16(unsigned dst, const void* src) {
    asm volatile("cp.async.cg.shared.global [%0], [%1], 16;"
                 :: "r"(dst), "l"(src));
}
#define CP_COMMIT() asm volatile("cp.async.commit_group;" ::: "memory")
#define CP_WAIT(n)  asm volatile("cp.async.wait_group %0;" :: "n"(n) : "memory")

// mma.sync m16n8k16 bf16 -> f32
__device__ __forceinline__ void mma16816(float* c, const unsigned* a, const unsigned* b) {
    asm volatile(
        "mma.sync.aligned.m16n8k16.row.col.f32.bf16.bf16.f32 "
        "{%0,%1,%2,%3}, {%4,%5,%6,%7}, {%8,%9}, {%0,%1,%2,%3};"
        : "+f"(c[0]), "+f"(c[1]), "+f"(c[2]), "+f"(c[3])
        : "r"(a[0]), "r"(a[1]), "r"(a[2]), "r"(a[3]), "r"(b[0]), "r"(b[1]));
}

__device__ __forceinline__ unsigned pack_bf2(float a, float b) {
    __nv_bfloat162 h = __floats2bfloat162_rn(a, b);
    return *(unsigned*)&h;
}

// ---------------------------------------------------------------------------
// Split fp32 -> bf16 hi/lo (vectorized, n4 = elements/4)
// ---------------------------------------------------------------------------
__global__ void split_kernel(const float* __restrict__ src,
                             __nv_bfloat16* __restrict__ hi,
                             __nv_bfloat16* __restrict__ lo, int n4) {
    int i = blockIdx.x * blockDim.x + threadIdx.x;
    if (i >= n4) return;
    float4 v = ((const float4*)src)[i];
    __nv_bfloat16 h0 = __float2bfloat16(v.x), h1 = __float2bfloat16(v.y);
    __nv_bfloat16 h2 = __float2bfloat16(v.z), h3 = __float2bfloat16(v.w);
    __nv_bfloat16 l0 = __float2bfloat16(v.x - __bfloat162float(h0));
    __nv_bfloat16 l1 = __float2bfloat16(v.y - __bfloat162float(h1));
    __nv_bfloat16 l2 = __float2bfloat16(v.z - __bfloat162float(h2));
    __nv_bfloat16 l3 = __float2bfloat16(v.w - __bfloat162float(h3));
    ((__nv_bfloat162*)hi)[2 * i]     = __nv_bfloat162(h0, h1);
    ((__nv_bfloat162*)hi)[2 * i + 1] = __nv_bfloat162(h2, h3);
    ((__nv_bfloat162*)lo)[2 * i]     = __nv_bfloat162(l0, l1);
    ((__nv_bfloat162*)lo)[2 * i + 1] = __nv_bfloat162(l2, l3);
}

// ---------------------------------------------------------------------------
// RoPE + split: reads fp32 t [S, KV_D], writes bf16 hi/lo (rotated)
// ---------------------------------------------------------------------------
__global__ void rope_split(const float* __restrict__ t,
                           const float* __restrict__ cosv,
                           const float* __restrict__ sinv,
                           __nv_bfloat16* __restrict__ th,
                           __nv_bfloat16* __restrict__ tl) {
    int idx = blockIdx.x * blockDim.x + threadIdx.x;
    const int total = S_LEN * N_KV * (HD / 2);
    if (idx >= total) return;
    int i = idx % (HD / 2);
    int kvh = (idx / (HD / 2)) % N_KV;
    int s = idx / ((HD / 2) * N_KV);
    size_t off = (size_t)s * KV_D + kvh * HD + 2 * i;
    float c = cosv[s * (HD / 2) + i];
    float sn = sinv[s * (HD / 2) + i];
    float a = t[off], b = t[off + 1];
    float o0 = a * c - b * sn;
    float o1 = a * sn + b * c;
    __nv_bfloat16 h0 = __float2bfloat16(o0), h1 = __float2bfloat16(o1);
    __nv_bfloat16 r0 = __float2bfloat16(o0 - __bfloat162float(h0));
    __nv_bfloat16 r1 = __float2bfloat16(o1 - __bfloat162float(h1));
    *(__nv_bfloat162*)(th + off) = __nv_bfloat162(h0, h1);
    *(__nv_bfloat162*)(tl + off) = __nv_bfloat162(r0, r1);
}

// ---------------------------------------------------------------------------
// Transpose + split: w[K,N] f32 -> wt[N,K] bf16 hi/lo
// ---------------------------------------------------------------------------
__global__ void transpose_split(const float* __restrict__ w,
                                __nv_bfloat16* __restrict__ th,
                                __nv_bfloat16* __restrict__ tl,
                                int Kdim, int Ndim) {
    __shared__ float tile[32][33];
    int n0 = blockIdx.x * 32, k0 = blockIdx.y * 32;
    int tx = threadIdx.x, ty = threadIdx.y;   // 32 x 8
    for (int r = ty; r < 32; r += 8)
        tile[r][tx] = w[(size_t)(k0 + r) * Ndim + n0 + tx];
    __syncthreads();
    for (int r = ty; r < 32; r += 8) {
        float v = tile[tx][r];
        __nv_bfloat16 h = __float2bfloat16(v);
        __nv_bfloat16 l = __float2bfloat16(v - __bfloat162float(h));
        size_t o = (size_t)(n0 + r) * Kdim + k0 + tx;
        th[o] = h;
        tl[o] = l;
    }
}

// ---------------------------------------------------------------------------
// mma.sync bf16x3 GEMM: C[M,N] = A[M,K] * Bt[N,K]^T  (fp32-accurate)
// ---------------------------------------------------------------------------
#define LDS_S 40
#define TILE_E (128 * LDS_S)
#define BUF_E (4 * TILE_E)
#define GEMM_SMEM_BYTES (2 * BUF_E * 2)

__global__ __launch_bounds__(256, 1)
void gemm_mma(int M, int N, int K,
              const __nv_bfloat16* __restrict__ Ah,
              const __nv_bfloat16* __restrict__ Al,
              const __nv_bfloat16* __restrict__ Bh,
              const __nv_bfloat16* __restrict__ Bl,
              float* __restrict__ C) {
    extern __shared__ __align__(16) __nv_bfloat16 s[];
    const int tid = threadIdx.x;
    const int wid = tid >> 5, lane = tid & 31;
    const int m0 = blockIdx.y * 128, n0 = blockIdx.x * 128;
    const int wm = (wid >> 2) * 64;
    const int wn = (wid & 3) * 32;
    const unsigned sbase = smem_u32(s);

    const int nch = K >> 5;

    auto issue = [&](int c, int buf) {
        const int k0 = c << 5;
        const unsigned b0 = sbase + buf * (BUF_E * 2);
#pragma unroll
        for (int it = 0; it < 2; it++) {
            const int idx = tid + it * 256;
            const int row = idx >> 2, seg = idx & 3;
            const unsigned so = (unsigned)(row * (LDS_S * 2) + seg * 16);
            const size_t ga = (size_t)(m0 + row) * K + k0 + seg * 8;
            const size_t gb = (size_t)(n0 + row) * K + k0 + seg * 8;
            cp_async16(b0 + so,                 Ah + ga);
            cp_async16(b0 + TILE_E * 2 + so,     Al + ga);
            cp_async16(b0 + TILE_E * 4 + so,     Bh + gb);
            cp_async16(b0 + TILE_E * 6 + so,     Bl + gb);
        }
    };

    float acc[4][4][4];
#pragma unroll
    for (int i = 0; i < 4; i++)
#pragma unroll
        for (int j = 0; j < 4; j++)
#pragma unroll
            for (int k = 0; k < 4; k++) acc[i][j][k] = 0.0f;

    issue(0, 0);
    CP_COMMIT();

    const int r = lane >> 2;
    const int q = (lane & 3) * 2;

    for (int c = 0; c < nch; c++) {
        if (c + 1 < nch) {
            issue(c + 1, (c + 1) & 1);
            CP_COMMIT();
            CP_WAIT(1);
        } else {
            CP_WAIT(0);
        }
        __syncthreads();

        const __nv_bfloat16* sb = s + (c & 1) * BUF_E;
        const __nv_bfloat16* sAh = sb;
        const __nv_bfloat16* sAl = sb + TILE_E;
        const __nv_bfloat16* sBh = sb + 2 * TILE_E;
        const __nv_bfloat16* sBl = sb + 3 * TILE_E;

#pragma unroll
        for (int kk = 0; kk < 2; kk++) {
            const int kc = kk * 16;
            unsigned ah[4][4], al[4][4], bh[4][2], bl[4][2];
#pragma unroll
            for (int mi = 0; mi < 4; mi++) {
                const int rb = (wm + mi * 16 + r) * LDS_S + kc + q;
                ah[mi][0] = *(const unsigned*)(sAh + rb);
                ah[mi][1] = *(const unsigned*)(sAh + rb + 8 * LDS_S);
                ah[mi][2] = *(const unsigned*)(sAh + rb + 8);
                ah[mi][3] = *(const unsigned*)(sAh + rb + 8 * LDS_S + 8);
                al[mi][0] = *(const unsigned*)(sAl + rb);
                al[mi][1] = *(const unsigned*)(sAl + rb + 8 * LDS_S);
                al[mi][2] = *(const unsigned*)(sAl + rb + 8);
                al[mi][3] = *(const unsigned*)(sAl + rb + 8 * LDS_S + 8);
            }
#pragma unroll
            for (int ni = 0; ni < 4; ni++) {
                const int rb = (wn + ni * 8 + r) * LDS_S + kc + q;
                bh[ni][0] = *(const unsigned*)(sBh + rb);
                bh[ni][1] = *(const unsigned*)(sBh + rb + 8);
                bl[ni][0] = *(const unsigned*)(sBl + rb);
                bl[ni][1] = *(const unsigned*)(sBl + rb + 8);
            }
#pragma unroll
            for (int mi = 0; mi < 4; mi++)
#pragma unroll
                for (int ni = 0; ni < 4; ni++) {
                    mma16816(acc[mi][ni], ah[mi], bh[ni]);
                    mma16816(acc[mi][ni], ah[mi], bl[ni]);
                    mma16816(acc[mi][ni], al[mi], bh[ni]);
                }
        }
        __syncthreads();
    }

#pragma unroll
    for (int mi = 0; mi < 4; mi++) {
#pragma unroll
        for (int ni = 0; ni < 4; ni++) {
            const int row = m0 + wm + mi * 16 + r;
            const int col = n0 + wn + ni * 8 + q;
            *(float2*)(C + (size_t)row * N + col) =
                make_float2(acc[mi][ni][0], acc[mi][ni][1]);
            *(float2*)(C + (size_t)(row + 8) * N + col) =
                make_float2(acc[mi][ni][2], acc[mi][ni][3]);
        }
    }
}

// ---------------------------------------------------------------------------
// Tensor-core flash attention (causal, GQA).
// Block: 64 q-rows x 1 head, 128 threads (4 warps, 16 rows each).
// QK: bf16x3; PV: Ph*Vh + Ph*Vl + Pl*Vh; P stays in registers.
// V smem key-pair-packed so PV B-fragments are single LDS.32.
// ---------------------------------------------------------------------------
#define KS_STRIDE 72   // bf16 units per K/Q smem row
#define VP_STRIDE 72   // u32 words per packed V row

__global__ __launch_bounds__(128)
void attn_mma(const __nv_bfloat16* __restrict__ Qh, const __nv_bfloat16* __restrict__ Ql,
              const __nv_bfloat16* __restrict__ Kh, const __nv_bfloat16* __restrict__ Kl,
              const __nv_bfloat16* __restrict__ Vh, const __nv_bfloat16* __restrict__ Vl,
              __nv_bfloat16* __restrict__ Yh, __nv_bfloat16* __restrict__ Yl) {
    __shared__ __align__(16) __nv_bfloat16 Ksh[64 * KS_STRIDE];
    __shared__ __align__(16) __nv_bfloat16 Ksl[64 * KS_STRIDE];
    __shared__ __align__(16) unsigned Vph[32 * VP_STRIDE];
    __shared__ __align__(16) unsigned Vpl[32 * VP_STRIDE];

    const int tid = threadIdx.x;
    const int wid = tid >> 5, lane = tid & 31;
    const int l0 = lane & 3, l1 = lane >> 2;
    const int q = l0 * 2;
    const int qt = blockIdx.x, h = blockIdx.y;
    const int kvh = h >> 2;
    const int q0 = qt * 64;
    const float scale = 0.125f;

    // --- Stage Q tile (reuse K buffers), extract fragments, release buffers ---
    {
        const int row = tid >> 1, sg = tid & 1;
        const uint4* gh = (const uint4*)(Qh + (size_t)(q0 + row) * D_MODEL + h * HD + sg * 32);
        const uint4* gl = (const uint4*)(Ql + (size_t)(q0 + row) * D_MODEL + h * HD + sg * 32);
        uint4* sh = (uint4*)(Ksh + row * KS_STRIDE + sg * 32);
        uint4* sl = (uint4*)(Ksl + row * KS_STRIDE + sg * 32);
#pragma unroll
        for (int u = 0; u < 4; u++) { sh[u] = gh[u]; sl[u] = gl[u]; }
    }
    __syncthreads();

    unsigned qfh[4][4], qfl[4][4];
    {
        const int qrow = wid * 16 + l1;
#pragma unroll
        for (int kc = 0; kc < 4; kc++) {
            const int base = qrow * KS_STRIDE + kc * 16 + q;
            qfh[kc][0] = *(const unsigned*)(Ksh + base);
            qfh[kc][1] = *(const unsigned*)(Ksh + base + 8 * KS_STRIDE);
            qfh[kc][2] = *(const unsigned*)(Ksh + base + 8);
            qfh[kc][3] = *(const unsigned*)(Ksh + base + 8 * KS_STRIDE + 8);
            qfl[kc][0] = *(const unsigned*)(Ksl + base);
            qfl[kc][1] = *(const unsigned*)(Ksl + base + 8 * KS_STRIDE);
            qfl[kc][2] = *(const unsigned*)(Ksl + base + 8);
            qfl[kc][3] = *(const unsigned*)(Ksl + base + 8 * KS_STRIDE + 8);
        }
    }
    __syncthreads();

    float o[8][4];
#pragma unroll
    for (int i = 0; i < 8; i++)
#pragma unroll
        for (int j = 0; j < 4; j++) o[i][j] = 0.0f;
    float m0 = -INFINITY, m1 = -INFINITY, ls0 = 0.0f, ls1 = 0.0f;

    const int gr0 = q0 + wid * 16 + l1;
    const int gr1 = gr0 + 8;

    for (int kt = 0; kt <= qt; kt++) {
        const int k0 = kt * 64;
        // Fill K tiles
        {
            const int row = tid >> 1, sg = tid & 1;
            const uint4* gh = (const uint4*)(Kh + (size_t)(k0 + row) * KV_D + kvh * HD + sg * 32);
            const uint4* gl = (const uint4*)(Kl + (size_t)(k0 + row) * KV_D + kvh * HD + sg * 32);
            uint4* sh = (uint4*)(Ksh + row * KS_STRIDE + sg * 32);
            uint4* sl = (uint4*)(Ksl + row * KS_STRIDE + sg * 32);
#pragma unroll
            for (int u = 0; u < 4; u++) { sh[u] = gh[u]; sl[u] = gl[u]; }
        }
        // Fill packed V tiles: word[kp][d] = {V[2kp][d], V[2kp+1][d]}
        {
            const int i = tid & 31;      // dim pair base d0 = 2i
            const int kpb = tid >> 5;    // 0..3
#pragma unroll
            for (int kp = kpb; kp < 32; kp += 4) {
                const size_t r0o = (size_t)(k0 + 2 * kp) * KV_D + kvh * HD + 2 * i;
                unsigned a = *(const unsigned*)(Vh + r0o);
                unsigned b = *(const unsigned*)(Vh + r0o + KV_D);
                Vph[kp * VP_STRIDE + 2 * i]     = __byte_perm(a, b, 0x5410);
                Vph[kp * VP_STRIDE + 2 * i + 1] = __byte_perm(a, b, 0x7632);
                unsigned c = *(const unsigned*)(Vl + r0o);
                unsigned d = *(const unsigned*)(Vl + r0o + KV_D);
                Vpl[kp * VP_STRIDE + 2 * i]     = __byte_perm(c, d, 0x5410);
                Vpl[kp * VP_STRIDE + 2 * i + 1] = __byte_perm(c, d, 0x7632);
            }
        }
        __syncthreads();

        // ---- S = Q K^T (bf16x3) ----
        float sc[8][4];
#pragma unroll
        for (int i = 0; i < 8; i++)
#pragma unroll
            for (int j = 0; j < 4; j++) sc[i][j] = 0.0f;

#pragma unroll
        for (int kc = 0; kc < 4; kc++) {
#pragma unroll
            for (int ni = 0; ni < 8; ni++) {
                const int base = (ni * 8 + l1) * KS_STRIDE + kc * 16 + q;
                unsigned bh[2], bl[2];
                bh[0] = *(const unsigned*)(Ksh + base);
                bh[1] = *(const unsigned*)(Ksh + base + 8);
                bl[0] = *(const unsigned*)(Ksl + base);
                bl[1] = *(const unsigned*)(Ksl + base + 8);
                mma16816(sc[ni], qfh[kc], bh);
                mma16816(sc[ni], qfh[kc], bl);
                mma16816(sc[ni], qfl[kc], bh);
            }
        }

        // ---- scale + causal mask ----
        if (kt == qt) {
#pragma unroll
            for (int ni = 0; ni < 8; ni++) {
                const int gc = k0 + ni * 8 + q;
                sc[ni][0] = (gc     <= gr0) ? sc[ni][0] * scale : -INFINITY;
                sc[ni][1] = (gc + 1 <= gr0) ? sc[ni][1] * scale : -INFINITY;
                sc[ni][2] = (gc     <= gr1) ? sc[ni][2] * scale : -INFINITY;
                sc[ni][3] = (gc + 1 <= gr1) ? sc[ni][3] * scale : -INFINITY;
            }
        } else {
#pragma unroll
            for (int ni = 0; ni < 8; ni++)
#pragma unroll
                for (int j = 0; j < 4; j++) sc[ni][j] *= scale;
        }

        // ---- online softmax ----
        float mx0 = -INFINITY, mx1 = -INFINITY;
#pragma unroll
        for (int ni = 0; ni < 8; ni++) {
            mx0 = fmaxf(mx0, fmaxf(sc[ni][0], sc[ni][1]));
            mx1 = fmaxf(mx1, fmaxf(sc[ni][2], sc[ni][3]));
        }
        mx0 = fmaxf(mx0, __shfl_xor_sync(0xffffffff, mx0, 1));
        mx0 = fmaxf(mx0, __shfl_xor_sync(0xffffffff, mx0, 2));
        mx1 = fmaxf(mx1, __shfl_xor_sync(0xffffffff, mx1, 1));
        mx1 = fmaxf(mx1, __shfl_xor_sync(0xffffffff, mx1, 2));

        const float mn0 = fmaxf(m0, mx0), mn1 = fmaxf(m1, mx1);
        const float a0 = __expf(m0 - mn0), a1 = __expf(m1 - mn1);
        m0 = mn0; m1 = mn1;

        float sum0 = 0.0f, sum1 = 0.0f;
#pragma unroll
        for (int ni = 0; ni < 8; ni++) {
            sc[ni][0] = __expf(sc[ni][0] - mn0);
            sc[ni][1] = __expf(sc[ni][1] - mn0);
            sc[ni][2] = __expf(sc[ni][2] - mn1);
            sc[ni][3] = __expf(sc[ni][3] - mn1);
            sum0 += sc[ni][0] + sc[ni][1];
            sum1 += sc[ni][2] + sc[ni][3];
        }
        sum0 += __shfl_xor_sync(0xffffffff, sum0, 1);
        sum0 += __shfl_xor_sync(0xffffffff, sum0, 2);
        sum1 += __shfl_xor_sync(0xffffffff, sum1, 1);
        sum1 += __shfl_xor_sync(0xffffffff, sum1, 2);
        ls0 = ls0 * a0 + sum0;
        ls1 = ls1 * a1 + sum1;

#pragma unroll
        for (int nd = 0; nd < 8; nd++) {
            o[nd][0] *= a0; o[nd][1] *= a0;
            o[nd][2] *= a1; o[nd][3] *= a1;
        }

        // ---- O += P V (Ph*Vh + Ph*Vl + Pl*Vh) ----
#pragma unroll
        for (int kc = 0; kc < 4; kc++) {
            unsigned pa[4], pl[4];
            // A-fragment of P for key chunk kc comes straight from sc regs
            {
                const float f00 = sc[2 * kc][0],     f01 = sc[2 * kc][1];
                const float f02 = sc[2 * kc][2],     f03 = sc[2 * kc][3];
                const float f10 = sc[2 * kc + 1][0], f11 = sc[2 * kc + 1][1];
                const float f12 = sc[2 * kc + 1][2], f13 = sc[2 * kc + 1][3];
                pa[0] = pack_bf2(f00, f01);
                pa[1] = pack_bf2(f02, f03);
                pa[2] = pack_bf2(f10, f11);
                pa[3] = pack_bf2(f12, f13);
                __nv_bfloat162 t0 = *(__nv_bfloat162*)&pa[0];
                __nv_bfloat162 t1 = *(__nv_bfloat162*)&pa[1];
                __nv_bfloat162 t2 = *(__nv_bfloat162*)&pa[2];
                __nv_bfloat162 t3 = *(__nv_bfloat162*)&pa[3];
                pl[0] = pack_bf2(f00 - __bfloat162float(t0.x), f01 - __bfloat162float(t0.y));
                pl[1] = pack_bf2(f02 - __bfloat162float(t1.x), f03 - __bfloat162float(t1.y));
                pl[2] = pack_bf2(f10 - __bfloat162float(t2.x), f11 - __bfloat162float(t2.y));
                pl[3] = pack_bf2(f12 - __bfloat162float(t3.x), f13 - __bfloat162float(t3.y));
            }
#pragma unroll
            for (int nd = 0; nd < 8; nd++) {
                const int widx = (kc * 8 + l0) * VP_STRIDE + nd * 8 + l1;
                unsigned vh[2], vl[2];
                vh[0] = Vph[widx];
                vh[1] = Vph[widx + 4 * VP_STRIDE];
                vl[0] = Vpl[widx];
                vl[1] = Vpl[widx + 4 * VP_STRIDE];
                mma16816(o[nd], pa, vh);
                mma16816(o[nd], pa, vl);
                mma16816(o[nd], pl, vh);
            }
        }
        __syncthreads();   // before next tile overwrites smem
    }

    // ---- epilogue: normalize, split to bf16 hi/lo, store ----
    const float inv0 = 1.0f / ls0, inv1 = 1.0f / ls1;
#pragma unroll
    for (int nd = 0; nd < 8; nd++) {
        const int col = h * HD + nd * 8 + q;
        {
            float y0 = o[nd][0] * inv0, y1 = o[nd][1] * inv0;
            unsigned hh = pack_bf2(y0, y1);
            __nv_bfloat162 t = *(__nv_bfloat162*)&hh;
            unsigned ll = pack_bf2(y0 - __bfloat162float(t.x), y1 - __bfloat162float(t.y));
            *(unsigned*)(Yh + (size_t)gr0 * D_MODEL + col) = hh;
            *(unsigned*)(Yl + (size_t)gr0 * D_MODEL + col) = ll;
        }
        {
            float y0 = o[nd][2] * inv1, y1 = o[nd][3] * inv1;
            unsigned hh = pack_bf2(y0, y1);
            __nv_bfloat162 t = *(__nv_bfloat162*)&hh;
            unsigned ll = pack_bf2(y0 - __bfloat162float(t.x), y1 - __bfloat162float(t.y));
            *(unsigned*)(Yh + (size_t)gr1 * D_MODEL + col) = hh;
            *(unsigned*)(Yl + (size_t)gr1 * D_MODEL + col) = ll;
        }
    }
}

// ---------------------------------------------------------------------------
// Launch
// ---------------------------------------------------------------------------
extern "C" void kernel_launch(void* const* d_in, const int* in_sizes, int n_in,
                              void* d_out, int out_size) {
    const float* x  = (const float*)d_in[0];
    const float* tc = (const float*)d_in[1];
    const float* ts = (const float*)d_in[2];
    const float* wq = (const float*)d_in[3];
    const float* wk = (const float*)d_in[4];
    const float* wv = (const float*)d_in[5];
    const float* wo = (const float*)d_in[6];
    float* out = (float*)d_out;

    float *Q, *K, *V;
    cudaGetSymbolAddress((void**)&Q, g_Q);
    cudaGetSymbolAddress((void**)&K, g_K);
    cudaGetSymbolAddress((void**)&V, g_V);
    __nv_bfloat16 *Ah, *Al, *Qh, *Ql, *Kh, *Kl, *Vh, *Vl, *Yh, *Yl;
    __nv_bfloat16 *Wqh, *Wql, *Wkh, *Wkl, *Wvh, *Wvl, *Woh, *Wol;
    cudaGetSymbolAddress((void**)&Ah, g_Ah);
    cudaGetSymbolAddress((void**)&Al, g_Al);
    cudaGetSymbolAddress((void**)&Qh, g_Qh);
    cudaGetSymbolAddress((void**)&Ql, g_Ql);
    cudaGetSymbolAddress((void**)&Kh, g_Kh);
    cudaGetSymbolAddress((void**)&Kl, g_Kl);
    cudaGetSymbolAddress((void**)&Vh, g_Vh);
    cudaGetSymbolAddress((void**)&Vl, g_Vl);
    cudaGetSymbolAddress((void**)&Yh, g_Yh);
    cudaGetSymbolAddress((void**)&Yl, g_Yl);
    cudaGetSymbolAddress((void**)&Wqh, g_Wqh);
    cudaGetSymbolAddress((void**)&Wql, g_Wql);
    cudaGetSymbolAddress((void**)&Wkh, g_Wkh);
    cudaGetSymbolAddress((void**)&Wkl, g_Wkl);
    cudaGetSymbolAddress((void**)&Wvh, g_Wvh);
    cudaGetSymbolAddress((void**)&Wvl, g_Wvl);
    cudaGetSymbolAddress((void**)&Woh, g_Woh);
    cudaGetSymbolAddress((void**)&Wol, g_Wol);

    cudaFuncSetAttribute(gemm_mma, cudaFuncAttributeMaxDynamicSharedMemorySize,
                         GEMM_SMEM_BYTES);

    // Split x -> bf16 hi/lo
    const int n4x = S_LEN * D_MODEL / 4;
    split_kernel<<<(n4x + 255) / 256, 256>>>(x, Ah, Al, n4x);

    // Transpose + split weights -> [N, K] bf16 hi/lo
    transpose_split<<<dim3(D_MODEL / 32, D_MODEL / 32), dim3(32, 8)>>>(wq, Wqh, Wql, D_MODEL, D_MODEL);
    transpose_split<<<dim3(KV_D / 32, D_MODEL / 32), dim3(32, 8)>>>(wk, Wkh, Wkl, D_MODEL, KV_D);
    transpose_split<<<dim3(KV_D / 32, D_MODEL / 32), dim3(32, 8)>>>(wv, Wvh, Wvl, D_MODEL, KV_D);
    transpose_split<<<dim3(D_MODEL / 32, D_MODEL / 32), dim3(32, 8)>>>(wo, Woh, Wol, D_MODEL, D_MODEL);

    // Projections (fp32 outputs)
    gemm_mma<<<dim3(D_MODEL / 128, S_LEN / 128), 256, GEMM_SMEM_BYTES>>>(
        S_LEN, D_MODEL, D_MODEL, Ah, Al, Wqh, Wql, Q);
    gemm_mma<<<dim3(KV_D / 128, S_LEN / 128), 256, GEMM_SMEM_BYTES>>>(
        S_LEN, KV_D, D_MODEL, Ah, Al, Wkh, Wkl, K);
    gemm_mma<<<dim3(KV_D / 128, S_LEN / 128), 256, GEMM_SMEM_BYTES>>>(
        S_LEN, KV_D, D_MODEL, Ah, Al, Wvh, Wvl, V);

    // RoPE + split K/V; split Q
    const int rope_total = S_LEN * N_KV * (HD / 2);
    rope_split<<<(rope_total + 255) / 256, 256>>>(K, tc, ts, Kh, Kl);
    rope_split<<<(rope_total + 255) / 256, 256>>>(V, tc, ts, Vh, Vl);
    split_kernel<<<(n4x + 255) / 256, 256>>>(Q, Qh, Ql, n4x);

    // Tensor-core attention -> Yh/Yl (bf16 hi/lo)
    attn_mma<<<dim3(S_LEN / 64, N_HEADS), 128>>>(Qh, Ql, Kh, Kl, Vh, Vl, Yh, Yl);

    // Output projection
    gemm_mma<<<dim3(D_MODEL / 128, S_LEN / 128), 256, GEMM_SMEM_BYTES>>>(
        S_LEN, D_MODEL, D_MODEL, Yh, Yl, Woh, Wol, out);
}